// round 1
// baseline (speedup 1.0000x reference)
#include <cuda_runtime.h>
#include <math.h>

#define Bb 4
#define Ss 1024
#define Dd 1024
#define Ee 8
#define DEe 128
#define SCALE (1.0f/32.0f)

// Scratch (allowed: static __device__ globals, no runtime allocation)
__device__ float g_scores[(size_t)Ee*Bb*Ss*Ss];  // 128 MB: per-pair raw scores
__device__ float g_attn[(size_t)Bb*Ss*Ss];       // 16 MB: summed prob maps

#define BM 64
#define BN 64
#define BK 16

// ---------------- Kernel A: scores[e,b,s,t] = SCALE * Qe[s,:]·Ke[t,:] ----------------
__global__ void __launch_bounds__(256) qk_kernel(const float* __restrict__ Q,
                                                 const float* __restrict__ K,
                                                 const int* __restrict__ emask) {
    int pair = blockIdx.z;              // pair = e*Bb + b, matches emask[E,B] layout
    if (emask[pair] == 0) return;
    int e = pair >> 2;                  // Bb == 4
    int b = pair & 3;
    int s0 = blockIdx.y * BM;
    int t0 = blockIdx.x * BN;

    __shared__ float As[BK][BM + 4];
    __shared__ float Bs[BK][BN + 4];

    const float* Qp = Q + ((size_t)b * Ss + s0) * Dd + e * DEe;
    const float* Kp = K + ((size_t)b * Ss + t0) * Dd + e * DEe;

    int tid = threadIdx.x;
    int tx = tid & 15, ty = tid >> 4;
    int lr = tid >> 2;                  // row within tile (0..63)
    int lk = (tid & 3) * 4;             // k offset (0,4,8,12)

    float acc[4][4] = {};

    for (int k0 = 0; k0 < DEe; k0 += BK) {
        float4 a = *(const float4*)(Qp + (size_t)lr * Dd + k0 + lk);
        float4 c = *(const float4*)(Kp + (size_t)lr * Dd + k0 + lk);
        As[lk + 0][lr] = a.x; As[lk + 1][lr] = a.y; As[lk + 2][lr] = a.z; As[lk + 3][lr] = a.w;
        Bs[lk + 0][lr] = c.x; Bs[lk + 1][lr] = c.y; Bs[lk + 2][lr] = c.z; Bs[lk + 3][lr] = c.w;
        __syncthreads();
        #pragma unroll
        for (int k = 0; k < BK; k++) {
            float av[4], bv[4];
            #pragma unroll
            for (int i = 0; i < 4; i++) av[i] = As[k][ty * 4 + i];
            #pragma unroll
            for (int j = 0; j < 4; j++) bv[j] = Bs[k][tx * 4 + j];
            #pragma unroll
            for (int i = 0; i < 4; i++)
                #pragma unroll
                for (int j = 0; j < 4; j++)
                    acc[i][j] += av[i] * bv[j];
        }
        __syncthreads();
    }

    float* outp = g_scores + ((size_t)pair * Ss + s0) * Ss + t0;
    #pragma unroll
    for (int i = 0; i < 4; i++)
        #pragma unroll
        for (int j = 0; j < 4; j++)
            outp[(size_t)(ty * 4 + i) * Ss + tx * 4 + j] = acc[i][j] * SCALE;
}

// ---------------- Kernel B: attn[b,s,t] = sum_routed_e softmax_t(scores[e,b,s,:]) ----------------
__global__ void __launch_bounds__(256) softmax_sum_kernel(const int* __restrict__ emask) {
    int row = blockIdx.x;               // b*Ss + s
    int b = row >> 10;                  // Ss == 1024
    int tid = threadIdx.x;

    __shared__ float red[256];
    float acc[4] = {0.f, 0.f, 0.f, 0.f};

    for (int e = 0; e < Ee; e++) {
        if (emask[e * Bb + b] == 0) continue;
        const float* sr = g_scores + ((size_t)(e * Bb) + b) * Ss * Ss + (size_t)(row & 1023) * Ss;
        float x[4];
        float lm = -1e30f;
        #pragma unroll
        for (int i = 0; i < 4; i++) { x[i] = sr[tid + 256 * i]; lm = fmaxf(lm, x[i]); }
        red[tid] = lm; __syncthreads();
        for (int off = 128; off > 0; off >>= 1) {
            if (tid < off) red[tid] = fmaxf(red[tid], red[tid + off]);
            __syncthreads();
        }
        float mx = red[0]; __syncthreads();
        float ls = 0.f;
        #pragma unroll
        for (int i = 0; i < 4; i++) { x[i] = __expf(x[i] - mx); ls += x[i]; }
        red[tid] = ls; __syncthreads();
        for (int off = 128; off > 0; off >>= 1) {
            if (tid < off) red[tid] += red[tid + off];
            __syncthreads();
        }
        float inv = 1.0f / red[0]; __syncthreads();
        #pragma unroll
        for (int i = 0; i < 4; i++) acc[i] += x[i] * inv;
    }

    float* ar = g_attn + (size_t)row * Ss;
    #pragma unroll
    for (int i = 0; i < 4; i++) ar[tid + 256 * i] = acc[i];
}

// ---------------- Kernel C: out[b,s,d] = (attn[b] @ V[b])[s,d] if d's expert in top2 else 0 ----------------
__global__ void __launch_bounds__(256) av_kernel(const float* __restrict__ V,
                                                 const float* __restrict__ rp,
                                                 float* __restrict__ outG) {
    int b = blockIdx.z;
    int d0 = blockIdx.x * BN;
    int s0 = blockIdx.y * BM;
    int tid = threadIdx.x;
    int tx = tid & 15, ty = tid >> 4;

    // top-2 experts for batch b from route_prob (ties -> lower index, matches jax top_k)
    float best = -1e30f, second = -1e30f;
    int bi = -1, si = -1;
    #pragma unroll
    for (int e = 0; e < Ee; e++) {
        float v = rp[b * Ee + e];
        if (v > best)       { second = best; si = bi; best = v; bi = e; }
        else if (v > second){ second = v; si = e; }
    }

    int e = d0 / DEe;
    if (e != bi && e != si) {
        #pragma unroll
        for (int i = 0; i < 4; i++)
            #pragma unroll
            for (int j = 0; j < 4; j++)
                outG[((size_t)b * Ss + s0 + ty * 4 + i) * Dd + d0 + tx * 4 + j] = 0.f;
        return;
    }

    __shared__ float As[BK][BM + 4];
    __shared__ float Bs[BK][BN + 4];

    const float* Ap = g_attn + ((size_t)b * Ss + s0) * Ss;
    const float* Vp = V + (size_t)b * Ss * Dd + d0;

    int lr = tid >> 2;                  // As: row 0..63
    int lk = (tid & 3) * 4;             // As: k offset
    int vk = tid >> 4;                  // Bs: k row 0..15
    int vn = (tid & 15) * 4;            // Bs: n offset

    float acc[4][4] = {};

    for (int k0 = 0; k0 < Ss; k0 += BK) {
        float4 a = *(const float4*)(Ap + (size_t)lr * Ss + k0 + lk);
        As[lk + 0][lr] = a.x; As[lk + 1][lr] = a.y; As[lk + 2][lr] = a.z; As[lk + 3][lr] = a.w;
        float4 v4 = *(const float4*)(Vp + (size_t)(k0 + vk) * Dd + vn);
        *(float4*)&Bs[vk][vn] = v4;
        __syncthreads();
        #pragma unroll
        for (int k = 0; k < BK; k++) {
            float av[4], bv[4];
            #pragma unroll
            for (int i = 0; i < 4; i++) av[i] = As[k][ty * 4 + i];
            #pragma unroll
            for (int j = 0; j < 4; j++) bv[j] = Bs[k][tx * 4 + j];
            #pragma unroll
            for (int i = 0; i < 4; i++)
                #pragma unroll
                for (int j = 0; j < 4; j++)
                    acc[i][j] += av[i] * bv[j];
        }
        __syncthreads();
    }

    #pragma unroll
    for (int i = 0; i < 4; i++)
        #pragma unroll
        for (int j = 0; j < 4; j++)
            outG[((size_t)b * Ss + s0 + ty * 4 + i) * Dd + d0 + tx * 4 + j] = acc[i][j];
}

extern "C" void kernel_launch(void* const* d_in, const int* in_sizes, int n_in,
                              void* d_out, int out_size) {
    const float* Q     = (const float*)d_in[0];
    const float* K     = (const float*)d_in[1];
    const float* V     = (const float*)d_in[2];
    const float* rp    = (const float*)d_in[3];
    const int*   emask = (const int*)  d_in[4];
    float* out = (float*)d_out;

    qk_kernel<<<dim3(Ss / BN, Ss / BM, Ee * Bb), 256>>>(Q, K, emask);
    softmax_sum_kernel<<<Bb * Ss, 256>>>(emask);
    av_kernel<<<dim3(Dd / BN, Ss / BM, Bb), 256>>>(V, rp, out);
}

// round 3
// speedup vs baseline: 2.0561x; 2.0561x over previous
#include <cuda_runtime.h>
#include <cstdint>
#include <math.h>

#define Bb 4
#define Ss 1024
#define Dd 1024
#define Ee 8
#define DEe 128
#define SCALEF 0.03125f

// ---------------- scratch (device globals; no runtime allocation) ----------------
__device__ float g_scores[(size_t)Ee * Bb * Ss * Ss];   // exp(score*scale), routed pairs only
__device__ float g_psum[(size_t)Ee * Bb * 8 * Ss];      // per (pair, t-tile) row sums of exp
__device__ float g_attn[(size_t)Bb * Ss * Ss];          // summed normalized probs
__device__ float g_vt[(size_t)Bb * 2 * DEe * Ss];       // transposed selected V slices [b][se][d][t]

#define STR 40   // smem row stride in floats (32 data + 8 pad -> conflict-free frag loads)

__device__ __forceinline__ uint32_t f2tf(float x) {
    uint32_t u;
    asm("cvt.rna.tf32.f32 %0, %1;" : "=r"(u) : "f"(x));
    return u;
}

__device__ __forceinline__ void mma_tf32(float* d, const uint32_t* a, const uint32_t* b) {
    asm volatile(
        "mma.sync.aligned.m16n8k8.row.col.f32.tf32.tf32.f32 "
        "{%0,%1,%2,%3}, {%4,%5,%6,%7}, {%8,%9}, {%0,%1,%2,%3};"
        : "+f"(d[0]), "+f"(d[1]), "+f"(d[2]), "+f"(d[3])
        : "r"(a[0]), "r"(a[1]), "r"(a[2]), "r"(a[3]), "r"(b[0]), "r"(b[1]));
}

// Load a 128-row x 32-col fp32 chunk (row stride ldg) into smem [row][k] tf32, stride STR.
__device__ __forceinline__ void load_chunk(const float* __restrict__ g, int ldg,
                                           uint32_t* __restrict__ s, int tid) {
#pragma unroll
    for (int i = 0; i < 4; i++) {
        int idx = tid + 256 * i;        // 1024 float4 slots
        int row = idx >> 3;
        int col = (idx & 7) << 2;
        float4 v = *(const float4*)(g + (size_t)row * ldg + col);
        uint4 o;
        o.x = f2tf(v.x); o.y = f2tf(v.y); o.z = f2tf(v.z); o.w = f2tf(v.w);
        *(uint4*)&s[row * STR + col] = o;
    }
}

// ---------------- Kernel 1: QK^T (tf32 mma.sync) + fused exp + row-sum partials ----------------
__global__ void __launch_bounds__(256) qk_mma(const float* __restrict__ Q,
                                              const float* __restrict__ K,
                                              const int* __restrict__ emask) {
    int pair = blockIdx.z;              // e*4 + b
    if (emask[pair] == 0) return;
    int e = pair >> 2, b = pair & 3;
    int t0 = blockIdx.x << 7;
    int s0 = blockIdx.y << 7;

    __shared__ uint32_t As[128 * STR];
    __shared__ uint32_t Bs[128 * STR];
    __shared__ float ps[128];

    int tid = threadIdx.x;
    int wid = tid >> 5, lane = tid & 31;
    int wm = wid & 1, wn = wid >> 1;    // warp grid: 2 (m) x 4 (n)
    int gq = lane >> 2, c = lane & 3;   // quad row / quad col

    if (tid < 128) ps[tid] = 0.f;

    const float* Ag = Q + (size_t)(b * Ss + s0) * Dd + e * DEe;
    const float* Bg = K + (size_t)(b * Ss + t0) * Dd + e * DEe;

    float acc[4][4][4] = {};

#pragma unroll 1
    for (int kc = 0; kc < 4; kc++) {
        load_chunk(Ag + kc * 32, Dd, As, tid);
        load_chunk(Bg + kc * 32, Dd, Bs, tid);
        __syncthreads();
#pragma unroll
        for (int ks = 0; ks < 4; ks++) {
            int k0 = ks * 8;
            uint32_t af[4][4], bf[4][2];
#pragma unroll
            for (int mt = 0; mt < 4; mt++) {
                int r0 = wm * 64 + mt * 16;
                af[mt][0] = As[(r0 + gq) * STR + k0 + c];
                af[mt][1] = As[(r0 + gq + 8) * STR + k0 + c];
                af[mt][2] = As[(r0 + gq) * STR + k0 + c + 4];
                af[mt][3] = As[(r0 + gq + 8) * STR + k0 + c + 4];
            }
#pragma unroll
            for (int nt = 0; nt < 4; nt++) {
                int n0 = wn * 32 + nt * 8;
                bf[nt][0] = Bs[(n0 + gq) * STR + k0 + c];
                bf[nt][1] = Bs[(n0 + gq) * STR + k0 + c + 4];
            }
#pragma unroll
            for (int mt = 0; mt < 4; mt++)
#pragma unroll
                for (int nt = 0; nt < 4; nt++)
                    mma_tf32(acc[mt][nt], af[mt], bf[nt]);
        }
        __syncthreads();
    }

    // Epilogue: exp + store + row-sum partials
    float* outbase = g_scores + (size_t)pair * Ss * Ss;
#pragma unroll
    for (int mt = 0; mt < 4; mt++) {
        int rl = wm * 64 + mt * 16 + gq;    // local row (lo half)
        float slo = 0.f, shi = 0.f;
#pragma unroll
        for (int nt = 0; nt < 4; nt++) {
            int colg = t0 + wn * 32 + nt * 8 + 2 * c;
            float e0 = __expf(acc[mt][nt][0] * SCALEF);
            float e1 = __expf(acc[mt][nt][1] * SCALEF);
            float e2 = __expf(acc[mt][nt][2] * SCALEF);
            float e3 = __expf(acc[mt][nt][3] * SCALEF);
            *(float2*)(outbase + (size_t)(s0 + rl) * Ss + colg)     = make_float2(e0, e1);
            *(float2*)(outbase + (size_t)(s0 + rl + 8) * Ss + colg) = make_float2(e2, e3);
            slo += e0 + e1; shi += e2 + e3;
        }
        slo += __shfl_xor_sync(0xFFFFFFFF, slo, 1);
        slo += __shfl_xor_sync(0xFFFFFFFF, slo, 2);
        shi += __shfl_xor_sync(0xFFFFFFFF, shi, 1);
        shi += __shfl_xor_sync(0xFFFFFFFF, shi, 2);
        if (c == 0) {
            atomicAdd(&ps[rl], slo);
            atomicAdd(&ps[rl + 8], shi);
        }
    }
    __syncthreads();
    if (tid < 128)
        g_psum[((size_t)pair * 8 + blockIdx.x) * Ss + s0 + tid] = ps[tid];
}

// ---------------- Kernel 2: attn[b,s,:] = sum_routed_e exp_row * inv_rowsum ----------------
__global__ void __launch_bounds__(256) combine_kernel(const int* __restrict__ emask) {
    int row = blockIdx.x;               // b*1024 + s
    int b = row >> 10, s = row & 1023;
    int tid = threadIdx.x;

    float a0 = 0.f, a1 = 0.f, a2 = 0.f, a3 = 0.f;
    for (int e = 0; e < Ee; e++) {
        int pair = e * Bb + b;
        if (emask[pair] == 0) continue;
        float sm = 0.f;
#pragma unroll
        for (int nt = 0; nt < 8; nt++)
            sm += g_psum[((size_t)pair * 8 + nt) * Ss + s];
        float inv = 1.0f / sm;
        const float* xr = g_scores + ((size_t)pair * Ss + s) * Ss;
        a0 += xr[tid]       * inv;
        a1 += xr[tid + 256] * inv;
        a2 += xr[tid + 512] * inv;
        a3 += xr[tid + 768] * inv;
    }
    float* ar = g_attn + (size_t)row * Ss;
    ar[tid] = a0; ar[tid + 256] = a1; ar[tid + 512] = a2; ar[tid + 768] = a3;
}

// ---------------- top-2 helper (ties -> lower index, matches jax top_k) ----------------
__device__ __forceinline__ void top2(const float* __restrict__ rp, int b, int& bi, int& si) {
    float best = -1e30f, second = -1e30f;
    bi = -1; si = -1;
#pragma unroll
    for (int e = 0; e < Ee; e++) {
        float v = rp[b * Ee + e];
        if (v > best)        { second = best; si = bi; best = v; bi = e; }
        else if (v > second) { second = v; si = e; }
    }
}

// ---------------- Kernel 3: transpose selected V slices -> g_vt[b][se][d][t] ----------------
__global__ void __launch_bounds__(256) vt_prep(const float* __restrict__ V,
                                               const float* __restrict__ rp) {
    int tt = blockIdx.x;                // 0..15, 64 t-rows each
    int se = blockIdx.y;                // 0 or 1
    int b  = blockIdx.z;
    int bi, si; top2(rp, b, bi, si);
    int eSel = (se == 0) ? bi : si;

    __shared__ float tile[64][132];
    int tid = threadIdx.x;
#pragma unroll
    for (int i = 0; i < 8; i++) {
        int v = tid + 256 * i;
        int r = v >> 5;
        int c = (v & 31) << 2;
        float4 val = *(const float4*)(V + ((size_t)(b * Ss + tt * 64 + r)) * Dd + eSel * DEe + c);
        *(float4*)&tile[r][c] = val;
    }
    __syncthreads();
#pragma unroll
    for (int i = 0; i < 8; i++) {
        int v = tid + 256 * i;
        int d = v >> 4;
        int t4 = (v & 15) << 2;
        float4 o = make_float4(tile[t4][d], tile[t4 + 1][d], tile[t4 + 2][d], tile[t4 + 3][d]);
        *(float4*)(g_vt + ((size_t)((b * 2 + se) * DEe + d)) * Ss + tt * 64 + t4) = o;
    }
}

// ---------------- Kernel 4: out = attn @ V (selected slices, tf32 mma.sync), zeros elsewhere --------
__global__ void __launch_bounds__(256) av_mma(const float* __restrict__ rp,
                                              float* __restrict__ outG) {
    int e  = blockIdx.x;                // expert (d-tile)
    int st = blockIdx.y;                // s-tile
    int b  = blockIdx.z;
    int tid = threadIdx.x;
    int wid = tid >> 5, lane = tid & 31;
    int s0 = st << 7;

    int bi, si; top2(rp, b, bi, si);
    if (e != bi && e != si) {
#pragma unroll
        for (int i = 0; i < 16; i++) {
            int v = tid + 256 * i;
            int r = v >> 5;
            int cc = (v & 31) << 2;
            *(float4*)(outG + ((size_t)(b * Ss + s0 + r)) * Dd + e * DEe + cc) =
                make_float4(0.f, 0.f, 0.f, 0.f);
        }
        return;
    }
    int se = (e == bi) ? 0 : 1;

    __shared__ uint32_t As[128 * STR];
    __shared__ uint32_t Bs[128 * STR];

    int wm = wid & 1, wn = wid >> 1;
    int gq = lane >> 2, c = lane & 3;

    const float* Ag = g_attn + (size_t)(b * Ss + s0) * Ss;
    const float* Bg = g_vt + (size_t)(b * 2 + se) * DEe * Ss;

    float acc[4][4][4] = {};

#pragma unroll 1
    for (int kc = 0; kc < 32; kc++) {
        load_chunk(Ag + kc * 32, Ss, As, tid);
        load_chunk(Bg + kc * 32, Ss, Bs, tid);
        __syncthreads();
#pragma unroll
        for (int ks = 0; ks < 4; ks++) {
            int k0 = ks * 8;
            uint32_t af[4][4], bf[4][2];
#pragma unroll
            for (int mt = 0; mt < 4; mt++) {
                int r0 = wm * 64 + mt * 16;
                af[mt][0] = As[(r0 + gq) * STR + k0 + c];
                af[mt][1] = As[(r0 + gq + 8) * STR + k0 + c];
                af[mt][2] = As[(r0 + gq) * STR + k0 + c + 4];
                af[mt][3] = As[(r0 + gq + 8) * STR + k0 + c + 4];
            }
#pragma unroll
            for (int nt = 0; nt < 4; nt++) {
                int n0 = wn * 32 + nt * 8;
                bf[nt][0] = Bs[(n0 + gq) * STR + k0 + c];
                bf[nt][1] = Bs[(n0 + gq) * STR + k0 + c + 4];
            }
#pragma unroll
            for (int mt = 0; mt < 4; mt++)
#pragma unroll
                for (int nt = 0; nt < 4; nt++)
                    mma_tf32(acc[mt][nt], af[mt], bf[nt]);
        }
        __syncthreads();
    }

#pragma unroll
    for (int mt = 0; mt < 4; mt++) {
        int rl = wm * 64 + mt * 16 + gq;
#pragma unroll
        for (int nt = 0; nt < 4; nt++) {
            int colg = e * DEe + wn * 32 + nt * 8 + 2 * c;
            *(float2*)(outG + ((size_t)(b * Ss + s0 + rl)) * Dd + colg) =
                make_float2(acc[mt][nt][0], acc[mt][nt][1]);
            *(float2*)(outG + ((size_t)(b * Ss + s0 + rl + 8)) * Dd + colg) =
                make_float2(acc[mt][nt][2], acc[mt][nt][3]);
        }
    }
}

// ---------------- launch ----------------
extern "C" void kernel_launch(void* const* d_in, const int* in_sizes, int n_in,
                              void* d_out, int out_size) {
    const float* Q     = (const float*)d_in[0];
    const float* K     = (const float*)d_in[1];
    const float* V     = (const float*)d_in[2];
    const float* rp    = (const float*)d_in[3];
    const int*   emask = (const int*)  d_in[4];
    float* out = (float*)d_out;

    vt_prep<<<dim3(16, 2, Bb), 256>>>(V, rp);
    qk_mma<<<dim3(8, 8, Ee * Bb), 256>>>(Q, K, emask);
    combine_kernel<<<Bb * Ss, 256>>>(emask);
    av_mma<<<dim3(Ee, 8, Bb), 256>>>(rp, out);
}

// round 4
// speedup vs baseline: 2.6482x; 1.2880x over previous
#include <cuda_runtime.h>
#include <cstdint>
#include <math.h>

#define Bb 4
#define Ss 1024
#define Dd 1024
#define Ee 8
#define DEe 128
#define SCALEF 0.03125f

// ---------------- scratch ----------------
__device__ float g_scores[(size_t)Ee * Bb * Ss * Ss];   // exp(score*scale), routed pairs only
__device__ float g_psum[(size_t)Ee * Bb * 8 * Ss];      // per (pair, t-tile) row sums
__device__ float g_attn[(size_t)Bb * Ss * Ss];          // summed normalized probs
__device__ float g_vt[(size_t)Bb * 2 * DEe * Ss];       // transposed selected V [b][se][d][t]

#define STR 36   // smem row stride (32 data + 4 pad): frag loads hit all 32 banks

__device__ __forceinline__ uint32_t f2tf(float x) {
    uint32_t u;
    asm("cvt.rna.tf32.f32 %0, %1;" : "=r"(u) : "f"(x));
    return u;
}

__device__ __forceinline__ void mma_tf32(float* d, const uint32_t* a, const uint32_t* b) {
    asm volatile(
        "mma.sync.aligned.m16n8k8.row.col.f32.tf32.tf32.f32 "
        "{%0,%1,%2,%3}, {%4,%5,%6,%7}, {%8,%9}, {%0,%1,%2,%3};"
        : "+f"(d[0]), "+f"(d[1]), "+f"(d[2]), "+f"(d[3])
        : "r"(a[0]), "r"(a[1]), "r"(a[2]), "r"(a[3]), "r"(b[0]), "r"(b[1]));
}

// ---------------- Kernel 1: QK^T (tf32 mma.sync, reg-prefetch pipelined) ----------------
__global__ void __launch_bounds__(256) qk_mma(const float* __restrict__ Q,
                                              const float* __restrict__ K,
                                              const int* __restrict__ emask) {
    int pair = blockIdx.z;              // e*4 + b
    if (emask[pair] == 0) return;
    int e = pair >> 2, b = pair & 3;
    int t0 = blockIdx.x << 7;
    int s0 = blockIdx.y << 7;

    __shared__ uint32_t As[128 * STR];
    __shared__ uint32_t Bs[128 * STR];
    __shared__ float ps[128];

    int tid = threadIdx.x;
    int wid = tid >> 5, lane = tid & 31;
    int wm = wid & 1, wn = wid >> 1;    // warps: 2 (m) x 4 (n)
    int gq = lane >> 2, c = lane & 3;

    if (tid < 128) ps[tid] = 0.f;

    const float* Ag = Q + (size_t)(b * Ss + s0) * Dd + e * DEe;
    const float* Bg = K + (size_t)(b * Ss + t0) * Dd + e * DEe;

    int lrow = tid >> 3, lcol = (tid & 7) << 2;  // chunk-load coords (2 rows apart per i)

    float acc[4][4][4] = {};
    float4 pa[4], pb[4];
#pragma unroll
    for (int i = 0; i < 4; i++) {
        int row = lrow + 32 * i;
        pa[i] = *(const float4*)(Ag + (size_t)row * Dd + lcol);
        pb[i] = *(const float4*)(Bg + (size_t)row * Dd + lcol);
    }

#pragma unroll 1
    for (int kc = 0; kc < 4; kc++) {
#pragma unroll
        for (int i = 0; i < 4; i++) {
            int row = lrow + 32 * i;
            uint4 oa, ob;
            oa.x = f2tf(pa[i].x); oa.y = f2tf(pa[i].y); oa.z = f2tf(pa[i].z); oa.w = f2tf(pa[i].w);
            ob.x = f2tf(pb[i].x); ob.y = f2tf(pb[i].y); ob.z = f2tf(pb[i].z); ob.w = f2tf(pb[i].w);
            *(uint4*)&As[row * STR + lcol] = oa;
            *(uint4*)&Bs[row * STR + lcol] = ob;
        }
        __syncthreads();
        if (kc < 3) {
#pragma unroll
            for (int i = 0; i < 4; i++) {
                int row = lrow + 32 * i;
                pa[i] = *(const float4*)(Ag + (size_t)row * Dd + (kc + 1) * 32 + lcol);
                pb[i] = *(const float4*)(Bg + (size_t)row * Dd + (kc + 1) * 32 + lcol);
            }
        }
#pragma unroll
        for (int ks = 0; ks < 4; ks++) {
            int k0 = ks * 8;
            uint32_t af[4][4], bf[4][2];
#pragma unroll
            for (int mt = 0; mt < 4; mt++) {
                int r0 = wm * 64 + mt * 16;
                af[mt][0] = As[(r0 + gq) * STR + k0 + c];
                af[mt][1] = As[(r0 + gq + 8) * STR + k0 + c];
                af[mt][2] = As[(r0 + gq) * STR + k0 + c + 4];
                af[mt][3] = As[(r0 + gq + 8) * STR + k0 + c + 4];
            }
#pragma unroll
            for (int nt = 0; nt < 4; nt++) {
                int n0 = wn * 32 + nt * 8;
                bf[nt][0] = Bs[(n0 + gq) * STR + k0 + c];
                bf[nt][1] = Bs[(n0 + gq) * STR + k0 + c + 4];
            }
#pragma unroll
            for (int mt = 0; mt < 4; mt++)
#pragma unroll
                for (int nt = 0; nt < 4; nt++)
                    mma_tf32(acc[mt][nt], af[mt], bf[nt]);
        }
        __syncthreads();
    }

    // Epilogue: exp + store + row-sum partials
    float* outbase = g_scores + (size_t)pair * Ss * Ss;
#pragma unroll
    for (int mt = 0; mt < 4; mt++) {
        int rl = wm * 64 + mt * 16 + gq;
        float slo = 0.f, shi = 0.f;
#pragma unroll
        for (int nt = 0; nt < 4; nt++) {
            int colg = t0 + wn * 32 + nt * 8 + 2 * c;
            float e0 = __expf(acc[mt][nt][0] * SCALEF);
            float e1 = __expf(acc[mt][nt][1] * SCALEF);
            float e2 = __expf(acc[mt][nt][2] * SCALEF);
            float e3 = __expf(acc[mt][nt][3] * SCALEF);
            *(float2*)(outbase + (size_t)(s0 + rl) * Ss + colg)     = make_float2(e0, e1);
            *(float2*)(outbase + (size_t)(s0 + rl + 8) * Ss + colg) = make_float2(e2, e3);
            slo += e0 + e1; shi += e2 + e3;
        }
        slo += __shfl_xor_sync(0xFFFFFFFF, slo, 1);
        slo += __shfl_xor_sync(0xFFFFFFFF, slo, 2);
        shi += __shfl_xor_sync(0xFFFFFFFF, shi, 1);
        shi += __shfl_xor_sync(0xFFFFFFFF, shi, 2);
        if (c == 0) {
            atomicAdd(&ps[rl], slo);
            atomicAdd(&ps[rl + 8], shi);
        }
    }
    __syncthreads();
    if (tid < 128)
        g_psum[((size_t)pair * 8 + blockIdx.x) * Ss + s0 + tid] = ps[tid];
}

// ---------------- Kernel 2: combine (float4) ----------------
__global__ void __launch_bounds__(256) combine_kernel(const int* __restrict__ emask) {
    int row = blockIdx.x;               // b*1024 + s
    int b = row >> 10, s = row & 1023;
    int tid = threadIdx.x;

    float4 a = make_float4(0.f, 0.f, 0.f, 0.f);
    for (int e = 0; e < Ee; e++) {
        int pair = e * Bb + b;
        if (emask[pair] == 0) continue;
        float sm = 0.f;
#pragma unroll
        for (int nt = 0; nt < 8; nt++)
            sm += g_psum[((size_t)pair * 8 + nt) * Ss + s];
        float inv = 1.0f / sm;
        float4 x = *(const float4*)(g_scores + ((size_t)pair * Ss + s) * Ss + tid * 4);
        a.x += x.x * inv; a.y += x.y * inv; a.z += x.z * inv; a.w += x.w * inv;
    }
    *(float4*)(g_attn + (size_t)row * Ss + tid * 4) = a;
}

// ---------------- top-2 (ties -> lower index) ----------------
__device__ __forceinline__ void top2(const float* __restrict__ rp, int b, int& bi, int& si) {
    float best = -1e30f, second = -1e30f;
    bi = -1; si = -1;
#pragma unroll
    for (int e = 0; e < Ee; e++) {
        float v = rp[b * Ee + e];
        if (v > best)        { second = best; si = bi; best = v; bi = e; }
        else if (v > second) { second = v; si = e; }
    }
}

// ---------------- Kernel 3: transpose selected V slices ----------------
__global__ void __launch_bounds__(256) vt_prep(const float* __restrict__ V,
                                               const float* __restrict__ rp) {
    int tt = blockIdx.x;
    int se = blockIdx.y;
    int b  = blockIdx.z;
    int bi, si; top2(rp, b, bi, si);
    int eSel = (se == 0) ? bi : si;

    __shared__ float tile[64][132];
    int tid = threadIdx.x;
#pragma unroll
    for (int i = 0; i < 8; i++) {
        int v = tid + 256 * i;
        int r = v >> 5;
        int c = (v & 31) << 2;
        float4 val = *(const float4*)(V + ((size_t)(b * Ss + tt * 64 + r)) * Dd + eSel * DEe + c);
        *(float4*)&tile[r][c] = val;
    }
    __syncthreads();
#pragma unroll
    for (int i = 0; i < 8; i++) {
        int v = tid + 256 * i;
        int d = v >> 4;
        int t4 = (v & 15) << 2;
        float4 o = make_float4(tile[t4][d], tile[t4 + 1][d], tile[t4 + 2][d], tile[t4 + 3][d]);
        *(float4*)(g_vt + ((size_t)((b * 2 + se) * DEe + d)) * Ss + tt * 64 + t4) = o;
    }
}

// ---------------- Kernel 4: out = attn @ V, 32x128 tiles, reg-prefetch pipelined ----------------
__global__ void __launch_bounds__(256) av_mma(const float* __restrict__ rp,
                                              float* __restrict__ outG) {
    int st = blockIdx.x;                // 0..31 s-tile (32 rows)
    int e  = blockIdx.y;                // expert
    int b  = blockIdx.z;
    int tid = threadIdx.x;
    int wid = tid >> 5, lane = tid & 31;
    int s0 = st << 5;

    int bi, si; top2(rp, b, bi, si);
    if (e != bi && e != si) {
#pragma unroll
        for (int i = 0; i < 4; i++) {
            int v = tid + 256 * i;
            int r = v >> 5;
            int cc = (v & 31) << 2;
            *(float4*)(outG + ((size_t)(b * Ss + s0 + r)) * Dd + e * DEe + cc) =
                make_float4(0.f, 0.f, 0.f, 0.f);
        }
        return;
    }
    int se = (e == bi) ? 0 : 1;

    __shared__ uint32_t As[32 * STR];
    __shared__ uint32_t Bs[128 * STR];

    int wm = wid & 1, wn = wid >> 1;
    int gq = lane >> 2, c = lane & 3;

    const float* Ag = g_attn + (size_t)(b * Ss + s0) * Ss;
    const float* Bg = g_vt + (size_t)(b * 2 + se) * DEe * Ss;

    int arow = tid >> 3, acol = (tid & 7) << 2;   // A: 32 rows
    float acc[4][4] = {};

    float4 pa = *(const float4*)(Ag + (size_t)arow * Ss + acol);
    float4 pb[4];
#pragma unroll
    for (int i = 0; i < 4; i++) {
        int idx = tid + 256 * i;
        int row = idx >> 3, col = (idx & 7) << 2;
        pb[i] = *(const float4*)(Bg + (size_t)row * Ss + col);
    }

#pragma unroll 1
    for (int kc = 0; kc < 32; kc++) {
        {
            uint4 o;
            o.x = f2tf(pa.x); o.y = f2tf(pa.y); o.z = f2tf(pa.z); o.w = f2tf(pa.w);
            *(uint4*)&As[arow * STR + acol] = o;
        }
#pragma unroll
        for (int i = 0; i < 4; i++) {
            int idx = tid + 256 * i;
            int row = idx >> 3, col = (idx & 7) << 2;
            uint4 o;
            o.x = f2tf(pb[i].x); o.y = f2tf(pb[i].y); o.z = f2tf(pb[i].z); o.w = f2tf(pb[i].w);
            *(uint4*)&Bs[row * STR + col] = o;
        }
        __syncthreads();
        if (kc < 31) {
            pa = *(const float4*)(Ag + (size_t)arow * Ss + (kc + 1) * 32 + acol);
#pragma unroll
            for (int i = 0; i < 4; i++) {
                int idx = tid + 256 * i;
                int row = idx >> 3, col = (idx & 7) << 2;
                pb[i] = *(const float4*)(Bg + (size_t)row * Ss + (kc + 1) * 32 + col);
            }
        }
#pragma unroll
        for (int ks = 0; ks < 4; ks++) {
            int k0 = ks * 8;
            uint32_t af[4], bf[4][2];
            af[0] = As[(wm * 16 + gq) * STR + k0 + c];
            af[1] = As[(wm * 16 + gq + 8) * STR + k0 + c];
            af[2] = As[(wm * 16 + gq) * STR + k0 + c + 4];
            af[3] = As[(wm * 16 + gq + 8) * STR + k0 + c + 4];
#pragma unroll
            for (int nt = 0; nt < 4; nt++) {
                int n0 = wn * 32 + nt * 8;
                bf[nt][0] = Bs[(n0 + gq) * STR + k0 + c];
                bf[nt][1] = Bs[(n0 + gq) * STR + k0 + c + 4];
            }
#pragma unroll
            for (int nt = 0; nt < 4; nt++)
                mma_tf32(acc[nt], af, bf[nt]);
        }
        __syncthreads();
    }

    int rl = wm * 16 + gq;
#pragma unroll
    for (int nt = 0; nt < 4; nt++) {
        int colg = e * DEe + wn * 32 + nt * 8 + 2 * c;
        *(float2*)(outG + ((size_t)(b * Ss + s0 + rl)) * Dd + colg) =
            make_float2(acc[nt][0], acc[nt][1]);
        *(float2*)(outG + ((size_t)(b * Ss + s0 + rl + 8)) * Dd + colg) =
            make_float2(acc[nt][2], acc[nt][3]);
    }
}

// ---------------- launch ----------------
extern "C" void kernel_launch(void* const* d_in, const int* in_sizes, int n_in,
                              void* d_out, int out_size) {
    const float* Q     = (const float*)d_in[0];
    const float* K     = (const float*)d_in[1];
    const float* V     = (const float*)d_in[2];
    const float* rp    = (const float*)d_in[3];
    const int*   emask = (const int*)  d_in[4];
    float* out = (float*)d_out;

    vt_prep<<<dim3(16, 2, Bb), 256>>>(V, rp);
    qk_mma<<<dim3(8, 8, Ee * Bb), 256>>>(Q, K, emask);
    combine_kernel<<<Bb * Ss, 256>>>(emask);
    av_mma<<<dim3(32, Ee, Bb), 256>>>(rp, out);
}

// round 6
// speedup vs baseline: 3.4238x; 1.2929x over previous
#include <cuda_runtime.h>
#include <cstdint>
#include <math.h>

#define Bb 4
#define Ss 1024
#define Dd 1024
#define Ee 8
#define DEe 128
#define SCALEF 0.03125f

// ---------------- scratch ----------------
__device__ float g_scores[(size_t)Ee * Bb * Ss * Ss];   // exp(score*scale), routed pairs only
__device__ float g_psum[(size_t)Ee * Bb * 8 * Ss];      // per (pair, t-tile) row sums
__device__ float g_attn[(size_t)Bb * Ss * Ss];          // tf32-rounded normalized probs
__device__ float g_vt[(size_t)Bb * 2 * DEe * Ss];       // tf32-rounded transposed V [b][se][d][t]

#define STR 36   // qk smem row stride (32 data + 4 pad)

__device__ __forceinline__ uint32_t f2tf(float x) {
    uint32_t u;
    asm("cvt.rna.tf32.f32 %0, %1;" : "=r"(u) : "f"(x));
    return u;
}

__device__ __forceinline__ void mma_tf32(float* d, const uint32_t* a, const uint32_t* b) {
    asm volatile(
        "mma.sync.aligned.m16n8k8.row.col.f32.tf32.tf32.f32 "
        "{%0,%1,%2,%3}, {%4,%5,%6,%7}, {%8,%9}, {%0,%1,%2,%3};"
        : "+f"(d[0]), "+f"(d[1]), "+f"(d[2]), "+f"(d[3])
        : "r"(a[0]), "r"(a[1]), "r"(a[2]), "r"(a[3]), "r"(b[0]), "r"(b[1]));
}

__device__ __forceinline__ void cp16(uint32_t* sdst, const float* gsrc) {
    uint32_t sa = (uint32_t)__cvta_generic_to_shared(sdst);
    asm volatile("cp.async.cg.shared.global [%0], [%1], 16;" :: "r"(sa), "l"(gsrc));
}
#define CP_COMMIT() asm volatile("cp.async.commit_group;" ::: "memory")
#define CP_WAIT1()  asm volatile("cp.async.wait_group 1;" ::: "memory")

// ---------------- Kernel 1: QK^T (tf32 mma.sync, reg-prefetch pipelined) ----------------
__global__ void __launch_bounds__(256) qk_mma(const float* __restrict__ Q,
                                              const float* __restrict__ K,
                                              const int* __restrict__ emask) {
    int pair = blockIdx.z;              // e*4 + b
    if (emask[pair] == 0) return;
    int e = pair >> 2, b = pair & 3;
    int t0 = blockIdx.x << 7;
    int s0 = blockIdx.y << 7;

    __shared__ uint32_t As[128 * STR];
    __shared__ uint32_t Bs[128 * STR];
    __shared__ float ps[128];

    int tid = threadIdx.x;
    int wid = tid >> 5, lane = tid & 31;
    int wm = wid & 1, wn = wid >> 1;    // warps: 2 (m) x 4 (n)
    int gq = lane >> 2, c = lane & 3;

    if (tid < 128) ps[tid] = 0.f;

    const float* Ag = Q + (size_t)(b * Ss + s0) * Dd + e * DEe;
    const float* Bg = K + (size_t)(b * Ss + t0) * Dd + e * DEe;

    int lrow = tid >> 3, lcol = (tid & 7) << 2;

    float acc[4][4][4] = {};
    float4 pa[4], pb[4];
#pragma unroll
    for (int i = 0; i < 4; i++) {
        int row = lrow + 32 * i;
        pa[i] = *(const float4*)(Ag + (size_t)row * Dd + lcol);
        pb[i] = *(const float4*)(Bg + (size_t)row * Dd + lcol);
    }

#pragma unroll 1
    for (int kc = 0; kc < 4; kc++) {
#pragma unroll
        for (int i = 0; i < 4; i++) {
            int row = lrow + 32 * i;
            uint4 oa, ob;
            oa.x = f2tf(pa[i].x); oa.y = f2tf(pa[i].y); oa.z = f2tf(pa[i].z); oa.w = f2tf(pa[i].w);
            ob.x = f2tf(pb[i].x); ob.y = f2tf(pb[i].y); ob.z = f2tf(pb[i].z); ob.w = f2tf(pb[i].w);
            *(uint4*)&As[row * STR + lcol] = oa;
            *(uint4*)&Bs[row * STR + lcol] = ob;
        }
        __syncthreads();
        if (kc < 3) {
#pragma unroll
            for (int i = 0; i < 4; i++) {
                int row = lrow + 32 * i;
                pa[i] = *(const float4*)(Ag + (size_t)row * Dd + (kc + 1) * 32 + lcol);
                pb[i] = *(const float4*)(Bg + (size_t)row * Dd + (kc + 1) * 32 + lcol);
            }
        }
#pragma unroll
        for (int ks = 0; ks < 4; ks++) {
            int k0 = ks * 8;
            uint32_t af[4][4], bf[4][2];
#pragma unroll
            for (int mt = 0; mt < 4; mt++) {
                int r0 = wm * 64 + mt * 16;
                af[mt][0] = As[(r0 + gq) * STR + k0 + c];
                af[mt][1] = As[(r0 + gq + 8) * STR + k0 + c];
                af[mt][2] = As[(r0 + gq) * STR + k0 + c + 4];
                af[mt][3] = As[(r0 + gq + 8) * STR + k0 + c + 4];
            }
#pragma unroll
            for (int nt = 0; nt < 4; nt++) {
                int n0 = wn * 32 + nt * 8;
                bf[nt][0] = Bs[(n0 + gq) * STR + k0 + c];
                bf[nt][1] = Bs[(n0 + gq) * STR + k0 + c + 4];
            }
#pragma unroll
            for (int mt = 0; mt < 4; mt++)
#pragma unroll
                for (int nt = 0; nt < 4; nt++)
                    mma_tf32(acc[mt][nt], af[mt], bf[nt]);
        }
        __syncthreads();
    }

    float* outbase = g_scores + (size_t)pair * Ss * Ss;
#pragma unroll
    for (int mt = 0; mt < 4; mt++) {
        int rl = wm * 64 + mt * 16 + gq;
        float slo = 0.f, shi = 0.f;
#pragma unroll
        for (int nt = 0; nt < 4; nt++) {
            int colg = t0 + wn * 32 + nt * 8 + 2 * c;
            float e0 = __expf(acc[mt][nt][0] * SCALEF);
            float e1 = __expf(acc[mt][nt][1] * SCALEF);
            float e2 = __expf(acc[mt][nt][2] * SCALEF);
            float e3 = __expf(acc[mt][nt][3] * SCALEF);
            *(float2*)(outbase + (size_t)(s0 + rl) * Ss + colg)     = make_float2(e0, e1);
            *(float2*)(outbase + (size_t)(s0 + rl + 8) * Ss + colg) = make_float2(e2, e3);
            slo += e0 + e1; shi += e2 + e3;
        }
        slo += __shfl_xor_sync(0xFFFFFFFF, slo, 1);
        slo += __shfl_xor_sync(0xFFFFFFFF, slo, 2);
        shi += __shfl_xor_sync(0xFFFFFFFF, shi, 1);
        shi += __shfl_xor_sync(0xFFFFFFFF, shi, 2);
        if (c == 0) {
            atomicAdd(&ps[rl], slo);
            atomicAdd(&ps[rl + 8], shi);
        }
    }
    __syncthreads();
    if (tid < 128)
        g_psum[((size_t)pair * 8 + blockIdx.x) * Ss + s0 + tid] = ps[tid];
}

// ---------------- Kernel 2: combine (float4, stores tf32-rounded) ----------------
__global__ void __launch_bounds__(256) combine_kernel(const int* __restrict__ emask) {
    int row = blockIdx.x;
    int b = row >> 10, s = row & 1023;
    int tid = threadIdx.x;

    float4 a = make_float4(0.f, 0.f, 0.f, 0.f);
    for (int e = 0; e < Ee; e++) {
        int pair = e * Bb + b;
        if (emask[pair] == 0) continue;
        float sm = 0.f;
#pragma unroll
        for (int nt = 0; nt < 8; nt++)
            sm += g_psum[((size_t)pair * 8 + nt) * Ss + s];
        float inv = 1.0f / sm;
        float4 x = *(const float4*)(g_scores + ((size_t)pair * Ss + s) * Ss + tid * 4);
        a.x += x.x * inv; a.y += x.y * inv; a.z += x.z * inv; a.w += x.w * inv;
    }
    uint4 o;
    o.x = f2tf(a.x); o.y = f2tf(a.y); o.z = f2tf(a.z); o.w = f2tf(a.w);
    *(uint4*)(g_attn + (size_t)row * Ss + tid * 4) = o;
}

// ---------------- top-2 (ties -> lower index) ----------------
__device__ __forceinline__ void top2(const float* __restrict__ rp, int b, int& bi, int& si) {
    float best = -1e30f, second = -1e30f;
    bi = -1; si = -1;
#pragma unroll
    for (int e = 0; e < Ee; e++) {
        float v = rp[b * Ee + e];
        if (v > best)        { second = best; si = bi; best = v; bi = e; }
        else if (v > second) { second = v; si = e; }
    }
}

// ---------------- Kernel 3: transpose selected V slices (stores tf32-rounded) ----------------
__global__ void __launch_bounds__(256) vt_prep(const float* __restrict__ V,
                                               const float* __restrict__ rp) {
    int tt = blockIdx.x;
    int se = blockIdx.y;
    int b  = blockIdx.z;
    int bi, si; top2(rp, b, bi, si);
    int eSel = (se == 0) ? bi : si;

    __shared__ float tile[64][132];
    int tid = threadIdx.x;
#pragma unroll
    for (int i = 0; i < 8; i++) {
        int v = tid + 256 * i;
        int r = v >> 5;
        int c = (v & 31) << 2;
        float4 val = *(const float4*)(V + ((size_t)(b * Ss + tt * 64 + r)) * Dd + eSel * DEe + c);
        *(float4*)&tile[r][c] = val;
    }
    __syncthreads();
#pragma unroll
    for (int i = 0; i < 8; i++) {
        int v = tid + 256 * i;
        int d = v >> 4;
        int t4 = (v & 15) << 2;
        uint4 o;
        o.x = f2tf(tile[t4][d]);     o.y = f2tf(tile[t4 + 1][d]);
        o.z = f2tf(tile[t4 + 2][d]); o.w = f2tf(tile[t4 + 3][d]);
        *(uint4*)(g_vt + ((size_t)((b * 2 + se) * DEe + d)) * Ss + tt * 64 + t4) = o;
    }
}

// ---------------- Kernel 4a: zero non-selected expert slices ----------------
__global__ void __launch_bounds__(256) zero_out(const float* __restrict__ rp,
                                                float* __restrict__ outG) {
    int e  = blockIdx.x;
    int st = blockIdx.y;                // 8 tiles of 128 rows
    int b  = blockIdx.z;
    int bi, si; top2(rp, b, bi, si);
    if (e == bi || e == si) return;
    int s0 = st << 7;
    int tid = threadIdx.x;
#pragma unroll
    for (int i = 0; i < 16; i++) {
        int v = tid + 256 * i;
        int r = v >> 5;
        int cc = (v & 31) << 2;
        *(float4*)(outG + ((size_t)(b * Ss + s0 + r)) * Dd + e * DEe + cc) =
            make_float4(0.f, 0.f, 0.f, 0.f);
    }
}

// ---------------- Kernel 4b: out = attn @ V (cp.async double-buffered) ----------------
#define AK 64                 // k chunk
#define ASTR 68               // smem row stride (64 data + 4 pad)
#define STAGE_U32 ((64 + 128) * ASTR)
#define AV_SMEM (2 * STAGE_U32 * 4)

__device__ __forceinline__ void av_issue(const float* Ag, const float* Bg, int kc,
                                         uint32_t* Abuf, uint32_t* Bbuf, int tid) {
#pragma unroll
    for (int i = 0; i < 4; i++) {       // A: 64 rows x 16 float4
        int idx = tid + 256 * i;
        int row = idx >> 4;
        int col = (idx & 15) << 2;
        cp16(&Abuf[row * ASTR + col], Ag + (size_t)row * Ss + kc * AK + col);
    }
#pragma unroll
    for (int i = 0; i < 8; i++) {       // B: 128 rows x 16 float4
        int idx = tid + 256 * i;
        int row = idx >> 4;
        int col = (idx & 15) << 2;
        cp16(&Bbuf[row * ASTR + col], Bg + (size_t)row * Ss + kc * AK + col);
    }
}

__global__ void __launch_bounds__(256) av_mma(const float* __restrict__ rp,
                                              float* __restrict__ outG) {
    int st = blockIdx.x;                // 0..15 (64 rows each)
    int se = blockIdx.y;                // 0..1 selected expert
    int b  = blockIdx.z;
    int tid = threadIdx.x;
    int wid = tid >> 5, lane = tid & 31;
    int s0 = st << 6;

    int bi, si; top2(rp, b, bi, si);
    int e = (se == 0) ? bi : si;

    extern __shared__ uint32_t sh[];
    uint32_t* Ab[2] = { sh,              sh + STAGE_U32 };
    uint32_t* Bbf[2] = { sh + 64 * ASTR, sh + STAGE_U32 + 64 * ASTR };

    int wm = wid & 1, wn = wid >> 1;    // 2 (m) x 4 (n)
    int gq = lane >> 2, c = lane & 31 & 3;

    const float* Ag = g_attn + (size_t)(b * Ss + s0) * Ss;
    const float* Bg = g_vt + (size_t)(b * 2 + se) * DEe * Ss;

    float acc[2][4][4] = {};

    av_issue(Ag, Bg, 0, Ab[0], Bbf[0], tid);
    CP_COMMIT();

#pragma unroll 1
    for (int kc = 0; kc < 16; kc++) {
        if (kc < 15) av_issue(Ag, Bg, kc + 1, Ab[(kc + 1) & 1], Bbf[(kc + 1) & 1], tid);
        CP_COMMIT();
        CP_WAIT1();
        __syncthreads();
        const uint32_t* As = Ab[kc & 1];
        const uint32_t* Bs = Bbf[kc & 1];
#pragma unroll
        for (int ks = 0; ks < 8; ks++) {
            int k0 = ks * 8;
            uint32_t af[2][4], bf[4][2];
#pragma unroll
            for (int mt = 0; mt < 2; mt++) {
                int r0 = wm * 32 + mt * 16;
                af[mt][0] = As[(r0 + gq) * ASTR + k0 + c];
                af[mt][1] = As[(r0 + gq + 8) * ASTR + k0 + c];
                af[mt][2] = As[(r0 + gq) * ASTR + k0 + c + 4];
                af[mt][3] = As[(r0 + gq + 8) * ASTR + k0 + c + 4];
            }
#pragma unroll
            for (int nt = 0; nt < 4; nt++) {
                int n0 = wn * 32 + nt * 8;
                bf[nt][0] = Bs[(n0 + gq) * ASTR + k0 + c];
                bf[nt][1] = Bs[(n0 + gq) * ASTR + k0 + c + 4];
            }
#pragma unroll
            for (int mt = 0; mt < 2; mt++)
#pragma unroll
                for (int nt = 0; nt < 4; nt++)
                    mma_tf32(acc[mt][nt], af[mt], bf[nt]);
        }
        __syncthreads();
    }

#pragma unroll
    for (int mt = 0; mt < 2; mt++) {
        int rl = wm * 32 + mt * 16 + gq;
#pragma unroll
        for (int nt = 0; nt < 4; nt++) {
            int colg = e * DEe + wn * 32 + nt * 8 + 2 * c;
            *(float2*)(outG + ((size_t)(b * Ss + s0 + rl)) * Dd + colg) =
                make_float2(acc[mt][nt][0], acc[mt][nt][1]);
            *(float2*)(outG + ((size_t)(b * Ss + s0 + rl + 8)) * Dd + colg) =
                make_float2(acc[mt][nt][2], acc[mt][nt][3]);
        }
    }
}

// ---------------- launch ----------------
extern "C" void kernel_launch(void* const* d_in, const int* in_sizes, int n_in,
                              void* d_out, int out_size) {
    const float* Q     = (const float*)d_in[0];
    const float* K     = (const float*)d_in[1];
    const float* V     = (const float*)d_in[2];
    const float* rp    = (const float*)d_in[3];
    const int*   emask = (const int*)  d_in[4];
    float* out = (float*)d_out;

    static bool attr_done = false;
    if (!attr_done) {
        cudaFuncSetAttribute(av_mma, cudaFuncAttributeMaxDynamicSharedMemorySize, AV_SMEM);
        attr_done = true;
    }

    vt_prep<<<dim3(16, 2, Bb), 256>>>(V, rp);
    qk_mma<<<dim3(8, 8, Ee * Bb), 256>>>(Q, K, emask);
    combine_kernel<<<Bb * Ss, 256>>>(emask);
    zero_out<<<dim3(Ee, 8, Bb), 256>>>(rp, out);
    av_mma<<<dim3(16, 2, Bb), 256, AV_SMEM>>>(rp, out);
}